// round 16
// baseline (speedup 1.0000x reference)
#include <cuda_runtime.h>
#include <cuda_fp16.h>
#include <cstdint>

// Problem constants: B=4, H=16, S=2048, D=64
#define S_LEN 2048
#define DH    64
#define BHN   64
#define BQ    64            // query rows per CTA
#define BKT   64            // key rows per tile
#define NTILE 32
#define NELEM ((size_t)BHN * S_LEN * DH)   // 8388608

// smem: Q hi [64x64] fp16 + ring region
//  pass A: 4 stages x 8KB (KH only)
//  pass B: 3 slots x 16KB {KH at +0, VH at +8192}
#define OFF_QH 0
#define OFF_ST 8192
#define SMEM_SZ (8192 + 3 * 16384)   // 57344  (3 CTAs/SM)
// post-loop reuse
#define OFF_RS  0           // float rsum[2][64]
#define OFF_INV 512         // float inv_s[64]
#define OFF_OSM 8192        // float Osm[64][64] (tail only)

typedef unsigned long long ull;

// fp16 hi copies of q,k,v + bit-packed mask
__device__ __align__(16) uint2 g_qhi[NELEM / 4];
__device__ __align__(16) uint2 g_khi[NELEM / 4];
__device__ __align__(16) uint2 g_vhi[NELEM / 4];
__device__ uint32_t g_mbits[(size_t)S_LEN * (S_LEN / 32)];   // [row][word]

// ---------------- helpers ----------------
__device__ __forceinline__ uint32_t s2u(const void* p) {
    uint32_t a;
    asm("{ .reg .u64 t; cvta.to.shared.u64 t, %1; cvt.u32.u64 %0, t; }" : "=r"(a) : "l"(p));
    return a;
}
__device__ __forceinline__ void ldsm4(uint32_t a, uint32_t* r) {
    asm volatile("ldmatrix.sync.aligned.m8n8.x4.shared.b16 {%0,%1,%2,%3}, [%4];"
                 : "=r"(r[0]), "=r"(r[1]), "=r"(r[2]), "=r"(r[3]) : "r"(a));
}
__device__ __forceinline__ void ldsm4t(uint32_t a, uint32_t* r) {
    asm volatile("ldmatrix.sync.aligned.m8n8.x4.trans.shared.b16 {%0,%1,%2,%3}, [%4];"
                 : "=r"(r[0]), "=r"(r[1]), "=r"(r[2]), "=r"(r[3]) : "r"(a));
}
__device__ __forceinline__ void mma_f16(float* d, const uint32_t* a,
                                        uint32_t b0, uint32_t b1) {
    asm volatile("mma.sync.aligned.m16n8k16.row.col.f32.f16.f16.f32 "
                 "{%0,%1,%2,%3},{%4,%5,%6,%7},{%8,%9},{%0,%1,%2,%3};"
                 : "+f"(d[0]), "+f"(d[1]), "+f"(d[2]), "+f"(d[3])
                 : "r"(a[0]), "r"(a[1]), "r"(a[2]), "r"(a[3]), "r"(b0), "r"(b1));
}
// pack two f32 -> f16x2 (lo in low half / element 0)
__device__ __forceinline__ uint32_t pk2(float lo, float hi) {
    uint32_t r;
    asm("cvt.rn.f16x2.f32 %0, %1, %2;" : "=r"(r) : "f"(hi), "f"(lo));
    return r;
}

__device__ __forceinline__ void cpa16(uint32_t dst, const void* src) {
    asm volatile("cp.async.cg.shared.global [%0], [%1], 16;" :: "r"(dst), "l"(src));
}
#define CPA_COMMIT() asm volatile("cp.async.commit_group;" ::: "memory")
#define CPA_WAIT2()  asm volatile("cp.async.wait_group 2;" ::: "memory")
#define CPA_WAIT1()  asm volatile("cp.async.wait_group 1;" ::: "memory")
#define CPA_WAIT0()  asm volatile("cp.async.wait_group 0;" ::: "memory")

// ---------------- pre-pass kernels ----------------
__global__ __launch_bounds__(256) void presplit_hi(const float4* __restrict__ src,
                                                   uint2* __restrict__ dhi)
{
    int i = blockIdx.x * blockDim.x + threadIdx.x;
    float4 t = src[i];
    dhi[i] = make_uint2(pk2(t.x, t.y), pk2(t.z, t.w));
}

__global__ __launch_bounds__(256) void pmask(const int* __restrict__ mask,
                                             uint32_t* __restrict__ bits)
{
    int idx = blockIdx.x * blockDim.x + threadIdx.x;   // word index
    const int4* m4 = (const int4*)mask + (size_t)idx * 8;
    uint32_t b = 0;
    #pragma unroll
    for (int i = 0; i < 8; ++i) {
        int4 v = m4[i];
        b |= (v.x != 0 ? 1u : 0u) << (i * 4);
        b |= (v.y != 0 ? 1u : 0u) << (i * 4 + 1);
        b |= (v.z != 0 ? 1u : 0u) << (i * 4 + 2);
        b |= (v.w != 0 ? 1u : 0u) << (i * 4 + 3);
    }
    bits[idx] = b;
}

__global__ __launch_bounds__(256, 3)
void attn_mma(float* __restrict__ out, float* __restrict__ p)
{
    extern __shared__ char sm[];
    const uint32_t sb = s2u(sm);
    const int tid = threadIdx.x;
    const int wid = tid >> 5, lane = tid & 31;
    const int rg = wid >> 1;                 // row group (16 rows)
    const int nhalf = wid & 1;               // 32-col half of tile
    const int bh = blockIdx.y;
    const int q0 = blockIdx.x * BQ;

    // cp.async mapping: chunk cc (16B), rows rr, rr+32
    const int cc = tid & 7, rr = tid >> 3;
    const uint32_t dcol = ((uint32_t)cc) << 4;
    const uint32_t drow0 = (uint32_t)rr * 128 + (dcol ^ (((uint32_t)rr & 7) << 4));
    const uint32_t drow1 = (uint32_t)(rr + 32) * 128 + (dcol ^ ((((uint32_t)rr + 32) & 7) << 4));
    const size_t srow0 = (size_t)rr * 128 + cc * 16;
    const size_t srow1 = (size_t)(rr + 32) * 128 + cc * 16;

    const char* khb = (const char*)g_khi + (size_t)bh * S_LEN * 128;
    const char* vhb = (const char*)g_vhi + (size_t)bh * S_LEN * 128;

    // epilogue thread mapping (m16n8 accum layout)
    const int r0l = rg * 16 + (lane >> 2);
    const int coff = (lane & 3) * 2;

    // ldmatrix lane mappings (XOR applied AFTER column adds)
    const int arow = rg * 16 + (lane & 15);
    const uint32_t arowoff = (uint32_t)arow * 128;
    const uint32_t acol0 = ((uint32_t)(lane >> 4)) << 4;
    const uint32_t axor = ((uint32_t)arow & 7) << 4;
    const int nrow = ((lane >> 4) << 3) + (lane & 7);
    const uint32_t nbase = (uint32_t)(nhalf * 32 + nrow) * 128;
    const uint32_t ncol0 = (((uint32_t)lane >> 3) & 1) << 4;
    const uint32_t nxor = ((uint32_t)(nrow & 7)) << 4;
    const int vrow = (((lane >> 3) & 1) << 3) + (lane & 7);
    const uint32_t vbase_off = (uint32_t)(nhalf * 32 + vrow) * 128;
    const uint32_t vcol0 = ((uint32_t)(lane >> 4)) << 4;
    const uint32_t vxor = ((uint32_t)(vrow & 7)) << 4;

    const uint32_t* mb0 = g_mbits + (size_t)(q0 + r0l) * 64 + nhalf;
    const uint32_t* mb1 = mb0 + 8 * 64;

    // ===== prologue: Q hi + pass-A 4-stage KH ring prime =====
    {
        const char* qh = (const char*)g_qhi + ((size_t)bh * S_LEN + q0) * 128;
        cpa16(sb + OFF_QH + drow0, qh + srow0);
        cpa16(sb + OFF_QH + drow1, qh + srow1);
        cpa16(sb + OFF_ST + drow0, khb + srow0);
        cpa16(sb + OFF_ST + drow1, khb + srow1);
        CPA_COMMIT();
        #pragma unroll
        for (int s = 1; s < 3; ++s) {
            const uint32_t st = sb + OFF_ST + (uint32_t)s * 8192;
            const size_t tb = (size_t)s * BKT * 128;
            cpa16(st + drow0, khb + tb + srow0);
            cpa16(st + drow1, khb + tb + srow1);
            CPA_COMMIT();
        }
    }
    CPA_WAIT2();          // Q + stage0 complete
    __syncthreads();

    // ---- hoist Q hi fragments (tile-invariant) into registers
    uint32_t qah[4][4];
    #pragma unroll
    for (int ks = 0; ks < 4; ++ks) {
        const uint32_t ao = arowoff + ((acol0 + (uint32_t)ks * 32) ^ axor);
        ldsm4(sb + OFF_QH + ao, qah[ks]);
    }

    float esum0 = 0.f, esum1 = 0.f;

    // ===== PASS A: approximate row sums (Qh.Kh fp16) =====
    for (int kb = 0; kb < NTILE; ++kb) {
        if (kb) { CPA_WAIT2(); __syncthreads(); }
        const uint32_t st = sb + OFF_ST + (uint32_t)(kb & 3) * 8192;
        const uint32_t w0 = mb0[kb * 2];
        const uint32_t w1 = mb1[kb * 2];

        float acc[4][4];
        #pragma unroll
        for (int i = 0; i < 4; ++i)
            #pragma unroll
            for (int c = 0; c < 4; ++c) acc[i][c] = 0.f;

        #pragma unroll
        for (int ks = 0; ks < 4; ++ks) {
            #pragma unroll
            for (int np = 0; np < 2; ++np) {
                uint32_t bh4[4];
                const uint32_t bo = nbase + (uint32_t)np * 2048 +
                                    ((ncol0 + (uint32_t)ks * 32) ^ nxor);
                ldsm4(st + bo, bh4);
                mma_f16(acc[np * 2], qah[ks], bh4[0], bh4[1]);
                mma_f16(acc[np * 2 + 1], qah[ks], bh4[2], bh4[3]);
            }
        }

        #pragma unroll
        for (int nt = 0; nt < 4; ++nt) {
            const int sh = coff + nt * 8;
            esum0 += ((w0 >> sh) & 1 ? __expf(acc[nt][0] * 0.125f) : 0.f)
                   + ((w0 >> (sh + 1)) & 1 ? __expf(acc[nt][1] * 0.125f) : 0.f);
            esum1 += ((w1 >> sh) & 1 ? __expf(acc[nt][2] * 0.125f) : 0.f)
                   + ((w1 >> (sh + 1)) & 1 ? __expf(acc[nt][3] * 0.125f) : 0.f);
        }

        if (kb + 3 < NTILE) {
            const uint32_t sn = sb + OFF_ST + (uint32_t)((kb + 3) & 3) * 8192;
            const size_t tb = (size_t)(kb + 3) * BKT * 128;
            cpa16(sn + drow0, khb + tb + srow0);
            cpa16(sn + drow1, khb + tb + srow1);
        }
        CPA_COMMIT();                        // keeps group count aligned
    }
    CPA_WAIT0();
    __syncthreads();

    // ===== prime pass-B ring {KH, VH} x2 slots (overlaps reduction) =====
    {
        #pragma unroll
        for (int s = 0; s < 2; ++s) {
            const uint32_t st = sb + OFF_ST + (uint32_t)s * 16384;
            const size_t tb = (size_t)s * BKT * 128;
            cpa16(st + drow0, khb + tb + srow0);          cpa16(st + drow1, khb + tb + srow1);
            cpa16(st + 8192 + drow0, vhb + tb + srow0);   cpa16(st + 8192 + drow1, vhb + tb + srow1);
            CPA_COMMIT();
        }
    }

    // ===== inter-pass: row sums -> inv =====
    esum0 += __shfl_xor_sync(0xffffffffu, esum0, 1);
    esum0 += __shfl_xor_sync(0xffffffffu, esum0, 2);
    esum1 += __shfl_xor_sync(0xffffffffu, esum1, 1);
    esum1 += __shfl_xor_sync(0xffffffffu, esum1, 2);
    float* rsum = (float*)(sm + OFF_RS);
    float* inv_s = (float*)(sm + OFF_INV);
    if ((lane & 3) == 0) {
        rsum[nhalf * 64 + r0l] = esum0;
        rsum[nhalf * 64 + r0l + 8] = esum1;
    }
    __syncthreads();
    if (tid < 64) inv_s[tid] = 1.f / (rsum[tid] + rsum[64 + tid]);
    __syncthreads();
    const float inv0 = inv_s[r0l], inv1 = inv_s[r0l + 8];

    float Oacc[8][4];
    #pragma unroll
    for (int i = 0; i < 8; ++i)
        #pragma unroll
        for (int c = 0; c < 4; ++c) Oacc[i][c] = 0.f;

    // ===== PASS B: S = Qh.Kh ; O += Êh.Vh ; normalized p write =====
    for (int kb = 0; kb < NTILE; ++kb) {
        CPA_WAIT1();
        __syncthreads();
        const uint32_t st = sb + OFF_ST + (uint32_t)(kb % 3) * 16384;
        const uint32_t w0 = mb0[kb * 2];
        const uint32_t w1 = mb1[kb * 2];

        float acc[4][4];
        #pragma unroll
        for (int i = 0; i < 4; ++i)
            #pragma unroll
            for (int c = 0; c < 4; ++c) acc[i][c] = 0.f;

        // ---- GEMM1: S = Qh.Kh  (1 product)
        #pragma unroll
        for (int ks = 0; ks < 4; ++ks) {
            #pragma unroll
            for (int np = 0; np < 2; ++np) {
                uint32_t bh4[4];
                const uint32_t bo = nbase + (uint32_t)np * 2048 +
                                    ((ncol0 + (uint32_t)ks * 32) ^ nxor);
                ldsm4(st + bo, bh4);
                mma_f16(acc[np * 2], qah[ks], bh4[0], bh4[1]);
                mma_f16(acc[np * 2 + 1], qah[ks], bh4[2], bh4[3]);
            }
        }

        // ---- epilogue: ê = exp * inv (normalized), p write, Êh frags
        uint32_t Eh[2][4];
        const int cb = kb * BKT + nhalf * 32 + coff;
        float* prow0 = p + ((size_t)(bh * S_LEN) + q0 + r0l) * S_LEN + cb;
        float* prow1 = prow0 + (size_t)8 * S_LEN;
        #pragma unroll
        for (int nt = 0; nt < 4; ++nt) {
            const int sh = coff + nt * 8;
            float e0 = (w0 >> sh) & 1 ? __expf(acc[nt][0] * 0.125f) * inv0 : 0.f;
            float e1 = (w0 >> (sh + 1)) & 1 ? __expf(acc[nt][1] * 0.125f) * inv0 : 0.f;
            float e2 = (w1 >> sh) & 1 ? __expf(acc[nt][2] * 0.125f) * inv1 : 0.f;
            float e3 = (w1 >> (sh + 1)) & 1 ? __expf(acc[nt][3] * 0.125f) * inv1 : 0.f;
            *(float2*)(prow0 + nt * 8) = make_float2(e0, e1);
            *(float2*)(prow1 + nt * 8) = make_float2(e2, e3);
            const int kk = nt >> 1, sl = (nt & 1) * 2;
            Eh[kk][sl + 0] = pk2(e0, e1);
            Eh[kk][sl + 1] = pk2(e2, e3);
        }

        // ---- GEMM2: O += Êh.Vh  (1 product)
        #pragma unroll
        for (int kk = 0; kk < 2; ++kk) {
            const uint32_t vrt = vbase_off + (uint32_t)kk * 2048;
            #pragma unroll
            for (int dt2 = 0; dt2 < 4; ++dt2) {
                uint32_t vh4[4];
                const uint32_t o = vrt + ((vcol0 + (uint32_t)dt2 * 32) ^ vxor);
                ldsm4t(st + 8192 + o, vh4);
                mma_f16(Oacc[dt2 * 2], Eh[kk], vh4[0], vh4[1]);
                mma_f16(Oacc[dt2 * 2 + 1], Eh[kk], vh4[2], vh4[3]);
            }
        }

        if (kb + 2 < NTILE) {
            const uint32_t sn = sb + OFF_ST + (uint32_t)((kb + 2) % 3) * 16384;
            const size_t tb = (size_t)(kb + 2) * BKT * 128;
            cpa16(sn + drow0, khb + tb + srow0);          cpa16(sn + drow1, khb + tb + srow1);
            cpa16(sn + 8192 + drow0, vhb + tb + srow0);   cpa16(sn + 8192 + drow1, vhb + tb + srow1);
        }
        CPA_COMMIT();
    }
    CPA_WAIT0();
    __syncthreads();      // ring reads done; smem reusable

    // ---- O combine across nhalf halves (already normalized) and store
    float* Osm = (float*)(sm + OFF_OSM);
    if (nhalf == 1) {
        #pragma unroll
        for (int dt = 0; dt < 8; ++dt) {
            *(float2*)&Osm[r0l * 64 + dt * 8 + coff] = make_float2(Oacc[dt][0], Oacc[dt][1]);
            *(float2*)&Osm[(r0l + 8) * 64 + dt * 8 + coff] = make_float2(Oacc[dt][2], Oacc[dt][3]);
        }
    }
    __syncthreads();
    if (nhalf == 0) {
        float* orow0 = out + ((size_t)(bh * S_LEN) + q0 + r0l) * DH + coff;
        float* orow1 = orow0 + 8 * DH;
        #pragma unroll
        for (int dt = 0; dt < 8; ++dt) {
            float2 a0 = *(float2*)&Osm[r0l * 64 + dt * 8 + coff];
            float2 a1 = *(float2*)&Osm[(r0l + 8) * 64 + dt * 8 + coff];
            *(float2*)(orow0 + dt * 8) = make_float2(Oacc[dt][0] + a0.x, Oacc[dt][1] + a0.y);
            *(float2*)(orow1 + dt * 8) = make_float2(Oacc[dt][2] + a1.x, Oacc[dt][3] + a1.y);
        }
    }
}

extern "C" void kernel_launch(void* const* d_in, const int* in_sizes, int n_in,
                              void* d_out, int out_size)
{
    const float* q    = (const float*)d_in[0];
    const float* k    = (const float*)d_in[1];
    const float* v    = (const float*)d_in[2];
    const int*   mask = (const int*)d_in[3];

    float* out = (float*)d_out;
    float* p   = out + NELEM;

    uint2 *qhi, *khi, *vhi;
    uint32_t* mbits;
    cudaGetSymbolAddress((void**)&qhi, g_qhi);
    cudaGetSymbolAddress((void**)&khi, g_khi);
    cudaGetSymbolAddress((void**)&vhi, g_vhi);
    cudaGetSymbolAddress((void**)&mbits, g_mbits);

    const unsigned gpre = (unsigned)(NELEM / 4 / 256);
    presplit_hi<<<gpre, 256>>>((const float4*)q, qhi);
    presplit_hi<<<gpre, 256>>>((const float4*)k, khi);
    presplit_hi<<<gpre, 256>>>((const float4*)v, vhi);
    pmask<<<(unsigned)((size_t)S_LEN * (S_LEN / 32) / 256), 256>>>(mask, mbits);

    cudaFuncSetAttribute(attn_mma, cudaFuncAttributeMaxDynamicSharedMemorySize, SMEM_SZ);
    dim3 g1(S_LEN / BQ, BHN);
    attn_mma<<<g1, 256, SMEM_SZ>>>(out, p);
}

// round 17
// speedup vs baseline: 1.0077x; 1.0077x over previous
#include <cuda_runtime.h>
#include <cuda_fp16.h>
#include <cstdint>

// Problem constants: B=4, H=16, S=2048, D=64
#define S_LEN 2048
#define DH    64
#define BHN   64
#define BQ    64            // query rows per CTA
#define BKT   64            // key rows per tile
#define NTILE 32
#define NELEM ((size_t)BHN * S_LEN * DH)   // 8388608

// smem: Q hi [64x64] fp16 + ring region
//  pass A: 4 stages x 8KB (KH only)
//  pass B: 4 slots x 16KB {KH at +0, VH at +8192}; V reads lag K by one tile
#define OFF_QH 0
#define OFF_ST 8192
#define SMEM_SZ (8192 + 4 * 16384)   // 73728 (2 CTAs/SM)
// post-loop reuse
#define OFF_RS  0           // float rsum[2][64]
#define OFF_INV 512         // float inv_s[64]
#define OFF_OSM 8192        // float Osm[64][64] (tail only)

typedef unsigned long long ull;

// fp16 hi copies of q,k,v + bit-packed mask
__device__ __align__(16) uint2 g_qhi[NELEM / 4];
__device__ __align__(16) uint2 g_khi[NELEM / 4];
__device__ __align__(16) uint2 g_vhi[NELEM / 4];
__device__ uint32_t g_mbits[(size_t)S_LEN * (S_LEN / 32)];   // [row][word]

// ---------------- helpers ----------------
__device__ __forceinline__ uint32_t s2u(const void* p) {
    uint32_t a;
    asm("{ .reg .u64 t; cvta.to.shared.u64 t, %1; cvt.u32.u64 %0, t; }" : "=r"(a) : "l"(p));
    return a;
}
__device__ __forceinline__ void ldsm4(uint32_t a, uint32_t* r) {
    asm volatile("ldmatrix.sync.aligned.m8n8.x4.shared.b16 {%0,%1,%2,%3}, [%4];"
                 : "=r"(r[0]), "=r"(r[1]), "=r"(r[2]), "=r"(r[3]) : "r"(a));
}
__device__ __forceinline__ void ldsm4t(uint32_t a, uint32_t* r) {
    asm volatile("ldmatrix.sync.aligned.m8n8.x4.trans.shared.b16 {%0,%1,%2,%3}, [%4];"
                 : "=r"(r[0]), "=r"(r[1]), "=r"(r[2]), "=r"(r[3]) : "r"(a));
}
__device__ __forceinline__ void mma_f16(float* d, const uint32_t* a,
                                        uint32_t b0, uint32_t b1) {
    asm volatile("mma.sync.aligned.m16n8k16.row.col.f32.f16.f16.f32 "
                 "{%0,%1,%2,%3},{%4,%5,%6,%7},{%8,%9},{%0,%1,%2,%3};"
                 : "+f"(d[0]), "+f"(d[1]), "+f"(d[2]), "+f"(d[3])
                 : "r"(a[0]), "r"(a[1]), "r"(a[2]), "r"(a[3]), "r"(b0), "r"(b1));
}
// pack two f32 -> f16x2 (lo in low half / element 0)
__device__ __forceinline__ uint32_t pk2(float lo, float hi) {
    uint32_t r;
    asm("cvt.rn.f16x2.f32 %0, %1, %2;" : "=r"(r) : "f"(hi), "f"(lo));
    return r;
}
// streaming store (evict-first; p is write-once)
__device__ __forceinline__ void stcs2(float* p, float a, float b) {
    asm volatile("st.global.cs.v2.f32 [%0], {%1, %2};" :: "l"(p), "f"(a), "f"(b) : "memory");
}

__device__ __forceinline__ void cpa16(uint32_t dst, const void* src) {
    asm volatile("cp.async.cg.shared.global [%0], [%1], 16;" :: "r"(dst), "l"(src));
}
#define CPA_COMMIT() asm volatile("cp.async.commit_group;" ::: "memory")
#define CPA_WAIT2()  asm volatile("cp.async.wait_group 2;" ::: "memory")
#define CPA_WAIT0()  asm volatile("cp.async.wait_group 0;" ::: "memory")

// ---------------- pre-pass kernels ----------------
__global__ __launch_bounds__(256) void presplit_hi(const float4* __restrict__ src,
                                                   uint2* __restrict__ dhi)
{
    int i = blockIdx.x * blockDim.x + threadIdx.x;
    float4 t = src[i];
    dhi[i] = make_uint2(pk2(t.x, t.y), pk2(t.z, t.w));
}

__global__ __launch_bounds__(256) void pmask(const int* __restrict__ mask,
                                             uint32_t* __restrict__ bits)
{
    int idx = blockIdx.x * blockDim.x + threadIdx.x;   // word index
    const int4* m4 = (const int4*)mask + (size_t)idx * 8;
    uint32_t b = 0;
    #pragma unroll
    for (int i = 0; i < 8; ++i) {
        int4 v = m4[i];
        b |= (v.x != 0 ? 1u : 0u) << (i * 4);
        b |= (v.y != 0 ? 1u : 0u) << (i * 4 + 1);
        b |= (v.z != 0 ? 1u : 0u) << (i * 4 + 2);
        b |= (v.w != 0 ? 1u : 0u) << (i * 4 + 3);
    }
    bits[idx] = b;
}

__global__ __launch_bounds__(256, 2)
void attn_mma(float* __restrict__ out, float* __restrict__ p)
{
    extern __shared__ char sm[];
    const uint32_t sb = s2u(sm);
    const int tid = threadIdx.x;
    const int wid = tid >> 5, lane = tid & 31;
    const int rg = wid >> 1;                 // row group (16 rows)
    const int nhalf = wid & 1;               // 32-col half of tile
    const int bh = blockIdx.y;
    const int q0 = blockIdx.x * BQ;

    // cp.async mapping: chunk cc (16B), rows rr, rr+32
    const int cc = tid & 7, rr = tid >> 3;
    const uint32_t dcol = ((uint32_t)cc) << 4;
    const uint32_t drow0 = (uint32_t)rr * 128 + (dcol ^ (((uint32_t)rr & 7) << 4));
    const uint32_t drow1 = (uint32_t)(rr + 32) * 128 + (dcol ^ ((((uint32_t)rr + 32) & 7) << 4));
    const size_t srow0 = (size_t)rr * 128 + cc * 16;
    const size_t srow1 = (size_t)(rr + 32) * 128 + cc * 16;

    const char* khb = (const char*)g_khi + (size_t)bh * S_LEN * 128;
    const char* vhb = (const char*)g_vhi + (size_t)bh * S_LEN * 128;

    // epilogue thread mapping (m16n8 accum layout)
    const int r0l = rg * 16 + (lane >> 2);
    const int coff = (lane & 3) * 2;

    // ldmatrix lane mappings (XOR applied AFTER column adds)
    const int arow = rg * 16 + (lane & 15);
    const uint32_t arowoff = (uint32_t)arow * 128;
    const uint32_t acol0 = ((uint32_t)(lane >> 4)) << 4;
    const uint32_t axor = ((uint32_t)arow & 7) << 4;
    const int nrow = ((lane >> 4) << 3) + (lane & 7);
    const uint32_t nbase = (uint32_t)(nhalf * 32 + nrow) * 128;
    const uint32_t ncol0 = (((uint32_t)lane >> 3) & 1) << 4;
    const uint32_t nxor = ((uint32_t)(nrow & 7)) << 4;
    const int vrow = (((lane >> 3) & 1) << 3) + (lane & 7);
    const uint32_t vbase_off = (uint32_t)(nhalf * 32 + vrow) * 128;
    const uint32_t vcol0 = ((uint32_t)(lane >> 4)) << 4;
    const uint32_t vxor = ((uint32_t)(vrow & 7)) << 4;

    const uint32_t* mb0 = g_mbits + (size_t)(q0 + r0l) * 64 + nhalf;
    const uint32_t* mb1 = mb0 + 8 * 64;

    // ===== prologue: Q hi + pass-A 4-stage KH ring prime =====
    {
        const char* qh = (const char*)g_qhi + ((size_t)bh * S_LEN + q0) * 128;
        cpa16(sb + OFF_QH + drow0, qh + srow0);
        cpa16(sb + OFF_QH + drow1, qh + srow1);
        cpa16(sb + OFF_ST + drow0, khb + srow0);
        cpa16(sb + OFF_ST + drow1, khb + srow1);
        CPA_COMMIT();
        #pragma unroll
        for (int s = 1; s < 3; ++s) {
            const uint32_t st = sb + OFF_ST + (uint32_t)s * 8192;
            const size_t tb = (size_t)s * BKT * 128;
            cpa16(st + drow0, khb + tb + srow0);
            cpa16(st + drow1, khb + tb + srow1);
            CPA_COMMIT();
        }
    }
    CPA_WAIT2();          // Q + stage0 complete
    __syncthreads();

    // ---- hoist Q hi fragments (tile-invariant) into registers
    uint32_t qah[4][4];
    #pragma unroll
    for (int ks = 0; ks < 4; ++ks) {
        const uint32_t ao = arowoff + ((acol0 + (uint32_t)ks * 32) ^ axor);
        ldsm4(sb + OFF_QH + ao, qah[ks]);
    }

    float esum0 = 0.f, esum1 = 0.f;

    // ===== PASS A: approximate row sums (Qh.Kh fp16) =====
    for (int kb = 0; kb < NTILE; ++kb) {
        if (kb) { CPA_WAIT2(); __syncthreads(); }
        const uint32_t st = sb + OFF_ST + (uint32_t)(kb & 3) * 8192;
        const uint32_t w0 = mb0[kb * 2];
        const uint32_t w1 = mb1[kb * 2];

        float acc[4][4];
        #pragma unroll
        for (int i = 0; i < 4; ++i)
            #pragma unroll
            for (int c = 0; c < 4; ++c) acc[i][c] = 0.f;

        #pragma unroll
        for (int ks = 0; ks < 4; ++ks) {
            #pragma unroll
            for (int np = 0; np < 2; ++np) {
                uint32_t bh4[4];
                const uint32_t bo = nbase + (uint32_t)np * 2048 +
                                    ((ncol0 + (uint32_t)ks * 32) ^ nxor);
                ldsm4(st + bo, bh4);
                mma_f16(acc[np * 2], qah[ks], bh4[0], bh4[1]);
                mma_f16(acc[np * 2 + 1], qah[ks], bh4[2], bh4[3]);
            }
        }

        #pragma unroll
        for (int nt = 0; nt < 4; ++nt) {
            const int sh = coff + nt * 8;
            esum0 += ((w0 >> sh) & 1 ? __expf(acc[nt][0] * 0.125f) : 0.f)
                   + ((w0 >> (sh + 1)) & 1 ? __expf(acc[nt][1] * 0.125f) : 0.f);
            esum1 += ((w1 >> sh) & 1 ? __expf(acc[nt][2] * 0.125f) : 0.f)
                   + ((w1 >> (sh + 1)) & 1 ? __expf(acc[nt][3] * 0.125f) : 0.f);
        }

        if (kb + 3 < NTILE) {
            const uint32_t sn = sb + OFF_ST + (uint32_t)((kb + 3) & 3) * 8192;
            const size_t tb = (size_t)(kb + 3) * BKT * 128;
            cpa16(sn + drow0, khb + tb + srow0);
            cpa16(sn + drow1, khb + tb + srow1);
        }
        CPA_COMMIT();                        // keeps group count aligned
    }
    CPA_WAIT0();
    __syncthreads();

    // ===== prime pass-B ring: g0={K0}, g1={K1,V0}, g2={K2,V1} =====
    {
        cpa16(sb + OFF_ST + drow0, khb + srow0);
        cpa16(sb + OFF_ST + drow1, khb + srow1);
        CPA_COMMIT();
        #pragma unroll
        for (int s = 1; s < 3; ++s) {
            const uint32_t stk = sb + OFF_ST + (uint32_t)s * 16384;
            const uint32_t stv = sb + OFF_ST + (uint32_t)(s - 1) * 16384 + 8192;
            const size_t tbk = (size_t)s * BKT * 128;
            const size_t tbv = (size_t)(s - 1) * BKT * 128;
            cpa16(stk + drow0, khb + tbk + srow0);   cpa16(stk + drow1, khb + tbk + srow1);
            cpa16(stv + drow0, vhb + tbv + srow0);   cpa16(stv + drow1, vhb + tbv + srow1);
            CPA_COMMIT();
        }
    }

    // ===== inter-pass: row sums -> inv (overlaps ring refill) =====
    esum0 += __shfl_xor_sync(0xffffffffu, esum0, 1);
    esum0 += __shfl_xor_sync(0xffffffffu, esum0, 2);
    esum1 += __shfl_xor_sync(0xffffffffu, esum1, 1);
    esum1 += __shfl_xor_sync(0xffffffffu, esum1, 2);
    float* rsum = (float*)(sm + OFF_RS);
    float* inv_s = (float*)(sm + OFF_INV);
    if ((lane & 3) == 0) {
        rsum[nhalf * 64 + r0l] = esum0;
        rsum[nhalf * 64 + r0l + 8] = esum1;
    }
    __syncthreads();
    if (tid < 64) inv_s[tid] = 1.f / (rsum[tid] + rsum[64 + tid]);
    __syncthreads();
    const float inv0 = inv_s[r0l], inv1 = inv_s[r0l + 8];

    float Oacc[8][4];
    #pragma unroll
    for (int i = 0; i < 8; ++i)
        #pragma unroll
        for (int c = 0; c < 4; ++c) Oacc[i][c] = 0.f;

    uint32_t Eh[2][4];   // Êh fragments of the PREVIOUS tile

    // ===== PASS B: GEMM1(kb) + GEMM2(kb-1) back-to-back, then epilogue(kb) =====
    // group math: at iter kb, committed = 3+kb groups; wait_group 2 -> done
    // through g(kb) = {K(kb), V(kb-1)}.
    for (int kb = 0; kb < NTILE; ++kb) {
        CPA_WAIT2();
        __syncthreads();
        const uint32_t stK = sb + OFF_ST + (uint32_t)(kb & 3) * 16384;
        const uint32_t stV = sb + OFF_ST + (uint32_t)((kb + 3) & 3) * 16384 + 8192;
        const uint32_t w0 = mb0[kb * 2];
        const uint32_t w1 = mb1[kb * 2];

        // ---- GEMM1(kb): S = Qh.Kh
        float acc[4][4];
        #pragma unroll
        for (int i = 0; i < 4; ++i)
            #pragma unroll
            for (int c = 0; c < 4; ++c) acc[i][c] = 0.f;

        #pragma unroll
        for (int ks = 0; ks < 4; ++ks) {
            #pragma unroll
            for (int np = 0; np < 2; ++np) {
                uint32_t bh4[4];
                const uint32_t bo = nbase + (uint32_t)np * 2048 +
                                    ((ncol0 + (uint32_t)ks * 32) ^ nxor);
                ldsm4(stK + bo, bh4);
                mma_f16(acc[np * 2], qah[ks], bh4[0], bh4[1]);
                mma_f16(acc[np * 2 + 1], qah[ks], bh4[2], bh4[3]);
            }
        }

        // ---- GEMM2(kb-1): O += Êh(kb-1).Vh(kb-1)  (fills GEMM1/epilogue bubble)
        if (kb) {
            #pragma unroll
            for (int kk = 0; kk < 2; ++kk) {
                const uint32_t vrt = vbase_off + (uint32_t)kk * 2048;
                #pragma unroll
                for (int dt2 = 0; dt2 < 4; ++dt2) {
                    uint32_t vh4[4];
                    const uint32_t o = vrt + ((vcol0 + (uint32_t)dt2 * 32) ^ vxor);
                    ldsm4t(stV + o, vh4);
                    mma_f16(Oacc[dt2 * 2], Eh[kk], vh4[0], vh4[1]);
                    mma_f16(Oacc[dt2 * 2 + 1], Eh[kk], vh4[2], vh4[3]);
                }
            }
        }

        // ---- epilogue(kb): ê = exp * inv, streaming p write, pack Êh
        const int cb = kb * BKT + nhalf * 32 + coff;
        float* prow0 = p + ((size_t)(bh * S_LEN) + q0 + r0l) * S_LEN + cb;
        float* prow1 = prow0 + (size_t)8 * S_LEN;
        #pragma unroll
        for (int nt = 0; nt < 4; ++nt) {
            const int sh = coff + nt * 8;
            float e0 = (w0 >> sh) & 1 ? __expf(acc[nt][0] * 0.125f) * inv0 : 0.f;
            float e1 = (w0 >> (sh + 1)) & 1 ? __expf(acc[nt][1] * 0.125f) * inv0 : 0.f;
            float e2 = (w1 >> sh) & 1 ? __expf(acc[nt][2] * 0.125f) * inv1 : 0.f;
            float e3 = (w1 >> (sh + 1)) & 1 ? __expf(acc[nt][3] * 0.125f) * inv1 : 0.f;
            stcs2(prow0 + nt * 8, e0, e1);
            stcs2(prow1 + nt * 8, e2, e3);
            const int kk = nt >> 1, sl = (nt & 1) * 2;
            Eh[kk][sl + 0] = pk2(e0, e1);
            Eh[kk][sl + 1] = pk2(e2, e3);
        }

        // ---- refill: K(kb+3) -> slot (kb+3)&3 ; V(kb+2) -> slot (kb+2)&3
        if (kb + 3 < NTILE) {
            const uint32_t sn = sb + OFF_ST + (uint32_t)((kb + 3) & 3) * 16384;
            const size_t tb = (size_t)(kb + 3) * BKT * 128;
            cpa16(sn + drow0, khb + tb + srow0);
            cpa16(sn + drow1, khb + tb + srow1);
        }
        if (kb + 2 < NTILE) {
            const uint32_t sv = sb + OFF_ST + (uint32_t)((kb + 2) & 3) * 16384 + 8192;
            const size_t tb = (size_t)(kb + 2) * BKT * 128;
            cpa16(sv + drow0, vhb + tb + srow0);
            cpa16(sv + drow1, vhb + tb + srow1);
        }
        CPA_COMMIT();
    }
    CPA_WAIT0();
    __syncthreads();      // V(31) complete + all ring reads done

    // ---- tail: GEMM2(31) from slot 3
    {
        const uint32_t stV = sb + OFF_ST + (uint32_t)((NTILE - 1) & 3) * 16384 + 8192;
        #pragma unroll
        for (int kk = 0; kk < 2; ++kk) {
            const uint32_t vrt = vbase_off + (uint32_t)kk * 2048;
            #pragma unroll
            for (int dt2 = 0; dt2 < 4; ++dt2) {
                uint32_t vh4[4];
                const uint32_t o = vrt + ((vcol0 + (uint32_t)dt2 * 32) ^ vxor);
                ldsm4t(stV + o, vh4);
                mma_f16(Oacc[dt2 * 2], Eh[kk], vh4[0], vh4[1]);
                mma_f16(Oacc[dt2 * 2 + 1], Eh[kk], vh4[2], vh4[3]);
            }
        }
    }
    __syncthreads();      // smem reusable

    // ---- O combine across nhalf halves (already normalized) and store
    float* Osm = (float*)(sm + OFF_OSM);
    if (nhalf == 1) {
        #pragma unroll
        for (int dt = 0; dt < 8; ++dt) {
            *(float2*)&Osm[r0l * 64 + dt * 8 + coff] = make_float2(Oacc[dt][0], Oacc[dt][1]);
            *(float2*)&Osm[(r0l + 8) * 64 + dt * 8 + coff] = make_float2(Oacc[dt][2], Oacc[dt][3]);
        }
    }
    __syncthreads();
    if (nhalf == 0) {
        float* orow0 = out + ((size_t)(bh * S_LEN) + q0 + r0l) * DH + coff;
        float* orow1 = orow0 + 8 * DH;
        #pragma unroll
        for (int dt = 0; dt < 8; ++dt) {
            float2 a0 = *(float2*)&Osm[r0l * 64 + dt * 8 + coff];
            float2 a1 = *(float2*)&Osm[(r0l + 8) * 64 + dt * 8 + coff];
            *(float2*)(orow0 + dt * 8) = make_float2(Oacc[dt][0] + a0.x, Oacc[dt][1] + a0.y);
            *(float2*)(orow1 + dt * 8) = make_float2(Oacc[dt][2] + a1.x, Oacc[dt][3] + a1.y);
        }
    }
}

extern "C" void kernel_launch(void* const* d_in, const int* in_sizes, int n_in,
                              void* d_out, int out_size)
{
    const float* q    = (const float*)d_in[0];
    const float* k    = (const float*)d_in[1];
    const float* v    = (const float*)d_in[2];
    const int*   mask = (const int*)d_in[3];

    float* out = (float*)d_out;
    float* p   = out + NELEM;

    uint2 *qhi, *khi, *vhi;
    uint32_t* mbits;
    cudaGetSymbolAddress((void**)&qhi, g_qhi);
    cudaGetSymbolAddress((void**)&khi, g_khi);
    cudaGetSymbolAddress((void**)&vhi, g_vhi);
    cudaGetSymbolAddress((void**)&mbits, g_mbits);

    const unsigned gpre = (unsigned)(NELEM / 4 / 256);
    presplit_hi<<<gpre, 256>>>((const float4*)q, qhi);
    presplit_hi<<<gpre, 256>>>((const float4*)k, khi);
    presplit_hi<<<gpre, 256>>>((const float4*)v, vhi);
    pmask<<<(unsigned)((size_t)S_LEN * (S_LEN / 32) / 256), 256>>>(mask, mbits);

    cudaFuncSetAttribute(attn_mma, cudaFuncAttributeMaxDynamicSharedMemorySize, SMEM_SZ);
    dim3 g1(S_LEN / BQ, BHN);
    attn_mma<<<g1, 256, SMEM_SZ>>>(out, p);
}